// round 10
// baseline (speedup 1.0000x reference)
#include <cuda_runtime.h>

// Problem shapes (fixed by the dataset).
constexpr int Bb = 16;
constexpr int Kk = 128;
constexpr int Nn = 8192;
constexpr int Mm = Nn + Kk;   // 8320
constexpr int Ww = Mm / 32;   // 260 bitmask words per batch

// Output packing: tuple concatenated in return order, all float32.
constexpr size_t OFF_ROIS = 0;
constexpr size_t OFF_LAB  = (size_t)Bb * Mm * 5;
constexpr size_t OFF_TGT  = OFF_LAB + (size_t)Bb * Mm;
constexpr size_t OFF_IW   = OFF_TGT + (size_t)Bb * Mm * 4;
constexpr size_t OFF_OW   = OFF_IW  + (size_t)Bb * Mm * 4;

// Scratch (no allocations allowed -> __device__ globals).
__device__ int      g_assign[Bb * Mm];
__device__ unsigned g_mask[Bb * Ww];
__device__ int      g_woff[Bb * Ww];
__device__ int      g_fgtot[Bb];

// ---------------------------------------------------------------------------
// Kernel 1: per-roi IoU max/argmax over K gt boxes. 1 roi/thread (max
// occupancy), +1 folded into precomputed x2+1/y2+1 on both sides, single
// clamp (negative ih auto-rejected by the sign of in_ in the comparator),
// division-free comparator inter_k*S_b > bI*S_k (ov = r/(1-r) monotone in
// r = inter/S). Appended-gt self-pairs resolved analytically (ov==1 exactly
// in the reference). Emits focal weights (original order) + fg bitmask.
// ---------------------------------------------------------------------------
__global__ __launch_bounds__(256) void k_iou(const float* __restrict__ rois,
                                             const float* __restrict__ gt,
                                             float* __restrict__ out) {
    const int b = blockIdx.y;
    const int t = threadIdx.x;
    const int m = blockIdx.x * 256 + t;
    const bool valid = (m < Mm);
    const int mm = valid ? m : (Mm - 1);

    __shared__ float4 sc[Kk];                    // gx1, gy1, gx2+1 (-1e30 if zero-area), gy2+1
    __shared__ __align__(16) float ssar[Kk];     // gt area (reference expression)

    const float* gtb = gt + (size_t)b * Kk * 5;
    if (t < Kk) {
        float x1 = gtb[t * 5 + 0], y1 = gtb[t * 5 + 1];
        float x2 = gtb[t * 5 + 2], y2 = gtb[t * 5 + 3];
        float w = x2 - x1 + 1.0f, h = y2 - y1 + 1.0f;
        bool zf = (w == 1.0f) && (h == 1.0f);
        sc[t] = make_float4(x1, y1, zf ? -1e30f : (x2 + 1.0f), y2 + 1.0f);
        ssar[t] = w * h;
    }
    __syncthreads();

    float x1, y1, x2, y2;
    if (mm < Nn) { const float* p = rois + ((size_t)b * Nn + mm) * 5;
                   x1 = p[1]; y1 = p[2]; x2 = p[3]; y2 = p[4]; }
    else         { const float* p = gtb + (size_t)(mm - Nn) * 5;
                   x1 = p[0]; y1 = p[1]; x2 = p[2]; y2 = p[3]; }
    const float aw = x2 - x1 + 1.0f;
    const float ah = y2 - y1 + 1.0f;
    const float aA = aw * ah;
    const float X2p = x2 + 1.0f, Y2p = y2 + 1.0f;

    float bI = 0.0f, bS = 1.0f;
    int arg = 0;

    #pragma unroll 2
    for (int kk = 0; kk < Kk; kk += 4) {
        const float4 sa4 = *(const float4*)&ssar[kk];
        const float sas[4] = {sa4.x, sa4.y, sa4.z, sa4.w};
        #pragma unroll
        for (int j = 0; j < 4; ++j) {
            const int k = kk + j;
            const float4 c = sc[k];
            float iw = fmaxf(fminf(X2p, c.z) - fmaxf(x1, c.x), 0.0f);
            float ih = fminf(Y2p, c.w) - fmaxf(y1, c.y);   // unclamped: ih<0 -> in_<=0 never wins
            float in_ = iw * ih;
            float S = aA + sas[j];
            bool p = in_ * bS > bI * S;
            bI = p ? in_ : bI;
            bS = p ? S : bS;
            arg = p ? k : arg;
        }
    }

    float mo; int a; bool fg;
    if ((aw == 1.0f) && (ah == 1.0f)) {        // zero-area roi (absent in data)
        mo = -1.0f; fg = false; a = 0;
    } else if (m >= Nn) {                      // appended gt: self-IoU == 1 exactly
        mo = 1.0f; fg = true; a = m - Nn;
    } else {
        mo = bI / (bS - bI);                   // one exact div, reference expression
        fg = (mo >= 0.5f);
        a = arg;
    }
    fg = fg && valid;
    const unsigned bal = __ballot_sync(0xffffffffu, fg);
    if (valid) {
        const int idx = b * Mm + m;
        if (fg) g_assign[idx] = a;
        const float om = 1.0f - mo;
        const float w = fg ? om * om : 0.0f;
        const float ow = (w > 0.0f) ? 1.0f : 0.0f;
        ((float4*)(out + OFF_IW))[idx] = make_float4(w, w, w, w);
        ((float4*)(out + OFF_OW))[idx] = make_float4(ow, ow, ow, ow);
        if ((t & 31) == 0) g_mask[b * Ww + (m >> 5)] = bal;   // Mm%32==0: word fully valid
    }
}

// ---------------------------------------------------------------------------
// Kernel 2: per-batch exclusive scan of per-word fg popcounts (260 words).
// Tiny (16 blocks); runs once so k_scatter is prologue-free.
// ---------------------------------------------------------------------------
__global__ __launch_bounds__(256) void k_scan() {
    const int b = blockIdx.x;
    const int t = threadIdx.x;
    const int lane = t & 31, wid = t >> 5;
    __shared__ int ws[8];

    const int w0 = 2 * t, w1 = 2 * t + 1;
    int c0 = (w0 < Ww) ? __popc(g_mask[b * Ww + w0]) : 0;
    int c1 = (w1 < Ww) ? __popc(g_mask[b * Ww + w1]) : 0;
    const int s = c0 + c1;

    int v = s;
    #pragma unroll
    for (int o = 1; o < 32; o <<= 1) {
        int n = __shfl_up_sync(0xffffffffu, v, o);
        if (lane >= o) v += n;
    }
    if (lane == 31) ws[wid] = v;
    __syncthreads();
    if (t < 8) {
        int x = ws[t];
        #pragma unroll
        for (int o = 1; o < 8; o <<= 1) {
            int n = __shfl_up_sync(0x000000ffu, x, o);
            if (t >= o) x += n;
        }
        ws[t] = x;
    }
    __syncthreads();
    const int excl = v - s + (wid ? ws[wid - 1] : 0);
    if (w0 < Ww) g_woff[b * Ww + w0] = excl;
    if (w1 < Ww) g_woff[b * Ww + w1] = excl + c0;
    if (t == 0) g_fgtot[b] = ws[7];
}

// ---------------------------------------------------------------------------
// Kernel 3: straight-line scatter (no smem, no syncs). Each warp maps to
// exactly one mask word (L1-broadcast loads). fg path (rare) gathers its
// assigned gt row for label + bbox_transform targets.
// ---------------------------------------------------------------------------
__global__ __launch_bounds__(256) void k_scatter(const float* __restrict__ rois,
                                                 const float* __restrict__ gt,
                                                 float* __restrict__ out) {
    const int b = blockIdx.y;
    const int m = blockIdx.x * 256 + threadIdx.x;
    if (m >= Mm) return;

    const int word = m >> 5, bit = m & 31;
    const unsigned mask = g_mask[b * Ww + word];   // warp-uniform -> broadcast
    const int woff = g_woff[b * Ww + word];
    const int tot = g_fgtot[b];
    const int pre = woff + __popc(mask & ((1u << bit) - 1u));  // fg before m
    const bool fg = (mask >> bit) & 1u;
    const int d = fg ? pre : tot + (m - pre);

    float x1, y1, x2, y2;
    if (m < Nn) {
        const float* r = rois + ((size_t)b * Nn + m) * 5;
        x1 = r[1]; y1 = r[2]; x2 = r[3]; y2 = r[4];
    } else {
        const float* r = gt + ((size_t)b * Kk + (m - Nn)) * 5;
        x1 = r[0]; y1 = r[1]; x2 = r[2]; y2 = r[3];
    }

    float* rb = out + OFF_ROIS + ((size_t)b * Mm + d) * 5;
    rb[0] = (float)b; rb[1] = x1; rb[2] = y1; rb[3] = x2; rb[4] = y2;

    float lab = 0.0f;
    float t0 = 0.0f, t1 = 0.0f, t2 = 0.0f, t3 = 0.0f;
    if (fg) {
        const int a = g_assign[b * Mm + m];
        const float* gb = gt + ((size_t)b * Kk + a) * 5;
        lab = gb[4];                                 // labels in {1..3}
        float ew = x2 - x1 + 1.0f, eh = y2 - y1 + 1.0f;
        float ecx = x1 + 0.5f * ew, ecy = y1 + 0.5f * eh;
        float gw = gb[2] - gb[0] + 1.0f, gh = gb[3] - gb[1] + 1.0f;
        float gcx = gb[0] + 0.5f * gw, gcy = gb[1] + 0.5f * gh;
        t0 = ((gcx - ecx) / ew) / 0.1f;
        t1 = ((gcy - ecy) / eh) / 0.1f;
        t2 = logf(gw / ew) / 0.2f;
        t3 = logf(gh / eh) / 0.2f;
    }
    out[OFF_LAB + (size_t)b * Mm + d] = lab;
    ((float4*)(out + OFF_TGT))[(size_t)b * Mm + d] = make_float4(t0, t1, t2, t3);
}

extern "C" void kernel_launch(void* const* d_in, const int* in_sizes, int n_in,
                              void* d_out, int out_size) {
    const float* rois = (const float*)d_in[0];   // (B, N, 5)
    const float* gt   = (const float*)d_in[1];   // (B, K, 5)
    float* out = (float*)d_out;

    dim3 grid((Mm + 255) / 256, Bb);             // 33 x 16
    k_iou<<<grid, 256>>>(rois, gt, out);
    k_scan<<<Bb, 256>>>();
    k_scatter<<<grid, 256>>>(rois, gt, out);
}

// round 11
// speedup vs baseline: 1.0762x; 1.0762x over previous
#include <cuda_runtime.h>

// Problem shapes (fixed by the dataset).
constexpr int Bb = 16;
constexpr int Kk = 128;
constexpr int Nn = 8192;
constexpr int Mm = Nn + Kk;   // 8320
constexpr int Ww = Mm / 32;   // 260 bitmask words per batch
constexpr int GX = 33;        // blocks per batch (33*256 = 8448 >= 8320)

// Output packing: tuple concatenated in return order, all float32.
constexpr size_t OFF_ROIS = 0;
constexpr size_t OFF_LAB  = (size_t)Bb * Mm * 5;
constexpr size_t OFF_TGT  = OFF_LAB + (size_t)Bb * Mm;
constexpr size_t OFF_IW   = OFF_TGT + (size_t)Bb * Mm * 4;
constexpr size_t OFF_OW   = OFF_IW  + (size_t)Bb * Mm * 4;

// Scratch (no allocations allowed -> __device__ globals).
__device__ unsigned g_mask[Bb * Ww];
__device__ int      g_cnt[Bb];   // monotone ticket counters: never reset, so the
                                 // barrier is correct across graph replays; the
                                 // outputs never depend on the counter value.

// ---------------------------------------------------------------------------
// Single fused kernel.
// Phase A: per-roi IoU max/argmax over K gt boxes (lean division-free loop,
//          proven in R9), focal weights (original order), fg bitmask.
// Barrier: per-batch software barrier over the 33 blocks sharing b.
//          All 528 blocks are co-resident (launch_bounds(256,4): 152*4=608),
//          so spinning cannot deadlock.
// Phase B: warp-local scan of the batch's 260 mask words -> dest index;
//          scatter rois/labels/targets with coords still live in registers.
// ---------------------------------------------------------------------------
__global__ __launch_bounds__(256, 4)
void k_fused(const float* __restrict__ rois,
             const float* __restrict__ gt,
             float* __restrict__ out) {
    const int b = blockIdx.y;
    const int t = threadIdx.x;
    const int m = blockIdx.x * 256 + t;
    const bool valid = (m < Mm);
    const int mm = valid ? m : (Mm - 1);

    __shared__ float4 sc[Kk];                    // gx1, gy1, gx2+1 (-1e30 if zero-area), gy2+1
    __shared__ __align__(16) float ssar[Kk];     // gt area (reference expression)
    __shared__ float slab[Kk];                   // gt label

    const float* gtb = gt + (size_t)b * Kk * 5;
    if (t < Kk) {
        float x1 = gtb[t * 5 + 0], y1 = gtb[t * 5 + 1];
        float x2 = gtb[t * 5 + 2], y2 = gtb[t * 5 + 3];
        float w = x2 - x1 + 1.0f, h = y2 - y1 + 1.0f;
        bool zf = (w == 1.0f) && (h == 1.0f);
        sc[t] = make_float4(x1, y1, zf ? -1e30f : (x2 + 1.0f), y2 + 1.0f);
        ssar[t] = w * h;
        slab[t] = gtb[t * 5 + 4];
    }
    __syncthreads();

    float x1, y1, x2, y2;
    if (mm < Nn) { const float* p = rois + ((size_t)b * Nn + mm) * 5;
                   x1 = p[1]; y1 = p[2]; x2 = p[3]; y2 = p[4]; }
    else         { const float* p = gtb + (size_t)(mm - Nn) * 5;
                   x1 = p[0]; y1 = p[1]; x2 = p[2]; y2 = p[3]; }
    const float aw = x2 - x1 + 1.0f;
    const float ah = y2 - y1 + 1.0f;
    const float aA = aw * ah;
    const float X2p = x2 + 1.0f, Y2p = y2 + 1.0f;

    float bI = 0.0f, bS = 1.0f;
    int arg = 0;

    #pragma unroll 2
    for (int kk = 0; kk < Kk; kk += 4) {
        const float4 sa4 = *(const float4*)&ssar[kk];
        const float sas[4] = {sa4.x, sa4.y, sa4.z, sa4.w};
        #pragma unroll
        for (int j = 0; j < 4; ++j) {
            const int k = kk + j;
            const float4 c = sc[k];
            float iw = fmaxf(fminf(X2p, c.z) - fmaxf(x1, c.x), 0.0f);
            float ih = fminf(Y2p, c.w) - fmaxf(y1, c.y);   // unclamped: ih<0 -> in_<=0 never wins
            float in_ = iw * ih;
            float S = aA + sas[j];
            bool p = in_ * bS > bI * S;
            bI = p ? in_ : bI;
            bS = p ? S : bS;
            arg = p ? k : arg;
        }
    }

    float mo; int a; bool fg;
    if ((aw == 1.0f) && (ah == 1.0f)) {        // zero-area roi (absent in data)
        mo = -1.0f; fg = false; a = 0;
    } else if (m >= Nn) {                      // appended gt: self-IoU == 1 exactly
        mo = 1.0f; fg = true; a = m - Nn;
    } else {
        mo = bI / (bS - bI);                   // one exact div, reference expression
        fg = (mo >= 0.5f);
        a = arg;
    }
    fg = fg && valid;
    const unsigned bal = __ballot_sync(0xffffffffu, fg);
    if (valid) {
        const int idx = b * Mm + m;
        const float om = 1.0f - mo;
        const float w = fg ? om * om : 0.0f;
        const float ow = (w > 0.0f) ? 1.0f : 0.0f;
        ((float4*)(out + OFF_IW))[idx] = make_float4(w, w, w, w);
        ((float4*)(out + OFF_OW))[idx] = make_float4(ow, ow, ow, ow);
        if ((t & 31) == 0) g_mask[b * Ww + (m >> 5)] = bal;   // words 0..259 each written once
    }

    // ---- per-batch barrier (monotone tickets) ----
    __syncthreads();                     // all warps of this block wrote their mask word
    if (t == 0) {
        __threadfence();                 // publish mask words
        const int ticket = atomicAdd(&g_cnt[b], 1);
        const int target = (ticket / GX + 1) * GX;
        while (atomicAdd(&g_cnt[b], 0) < target) __nanosleep(64);
        __threadfence();                 // acquire other blocks' mask words
    }
    __syncthreads();

    if (!valid) return;

    // ---- warp-local prefix over the batch's mask words (no smem, no syncs) ----
    const int word = m >> 5;             // warp-uniform (256-thread blocks, aligned)
    const int lane = t & 31;
    int tot = 0, pre = 0;
    unsigned myw = 0;
    #pragma unroll 4
    for (int w = lane; w < Ww; w += 32) {  // coalesced, L2-hot (16KB table)
        const unsigned mk = g_mask[b * Ww + w];
        const int c = __popc(mk);
        tot += c;
        if (w < word) pre += c;
        if (w == word) myw = mk;
    }
    #pragma unroll
    for (int o = 16; o > 0; o >>= 1) {
        tot += __shfl_xor_sync(0xffffffffu, tot, o);
        pre += __shfl_xor_sync(0xffffffffu, pre, o);
    }
    myw = __shfl_sync(0xffffffffu, myw, word & 31);
    pre += __popc(myw & ((1u << lane) - 1u));       // fg before m within word
    const int d = fg ? pre : tot + (m - pre);

    // ---- scatter with live registers ----
    float* rb = out + OFF_ROIS + ((size_t)b * Mm + d) * 5;
    rb[0] = (float)b; rb[1] = x1; rb[2] = y1; rb[3] = x2; rb[4] = y2;

    float lab = 0.0f;
    float t0 = 0.0f, t1 = 0.0f, t2 = 0.0f, t3 = 0.0f;
    if (fg) {
        const float4 c = sc[a];                    // assigned gt, smem-resident
        lab = slab[a];                             // labels in {1..3}
        float ew = x2 - x1 + 1.0f, eh = y2 - y1 + 1.0f;
        float ecx = x1 + 0.5f * ew, ecy = y1 + 0.5f * eh;
        float gw = c.z - c.x, gh = c.w - c.y;      // (x2+1)-x1: <=1 ulp vs reference
        float gcx = c.x + 0.5f * gw, gcy = c.y + 0.5f * gh;
        t0 = ((gcx - ecx) / ew) / 0.1f;
        t1 = ((gcy - ecy) / eh) / 0.1f;
        t2 = logf(gw / ew) / 0.2f;
        t3 = logf(gh / eh) / 0.2f;
    }
    out[OFF_LAB + (size_t)b * Mm + d] = lab;
    ((float4*)(out + OFF_TGT))[(size_t)b * Mm + d] = make_float4(t0, t1, t2, t3);
}

extern "C" void kernel_launch(void* const* d_in, const int* in_sizes, int n_in,
                              void* d_out, int out_size) {
    const float* rois = (const float*)d_in[0];   // (B, N, 5)
    const float* gt   = (const float*)d_in[1];   // (B, K, 5)
    float* out = (float*)d_out;

    dim3 grid(GX, Bb);                           // 33 x 16 = 528 blocks, one wave
    k_fused<<<grid, 256>>>(rois, gt, out);
}

// round 12
// speedup vs baseline: 1.0997x; 1.0218x over previous
#include <cuda_runtime.h>

// Problem shapes (fixed by the dataset).
constexpr int Bb = 16;
constexpr int Kk = 128;
constexpr int Nn = 8192;
constexpr int Mm = Nn + Kk;   // 8320
constexpr int Ww = Mm / 32;   // 260 bitmask words per batch
constexpr int GX = 19;        // blocks per batch (19*448 = 8512 >= 8320)
constexpr int TT = 448;       // threads per block (14 warps)

// Output packing: tuple concatenated in return order, all float32.
constexpr size_t OFF_ROIS = 0;
constexpr size_t OFF_LAB  = (size_t)Bb * Mm * 5;
constexpr size_t OFF_TGT  = OFF_LAB + (size_t)Bb * Mm;
constexpr size_t OFF_IW   = OFF_TGT + (size_t)Bb * Mm * 4;
constexpr size_t OFF_OW   = OFF_IW  + (size_t)Bb * Mm * 4;

// Scratch (no allocations allowed -> __device__ globals).
__device__ unsigned g_mask[Bb * Ww];
__device__ int      g_cnt[Bb];   // monotone ticket counters: never reset, so the
                                 // barrier is correct across graph replays; the
                                 // outputs never depend on the counter value.

// ---------------------------------------------------------------------------
// Single fused kernel, balanced single wave: 304 blocks = exactly 2/SM on
// 152 SMs (launch_bounds(448,2) guarantees co-residency -> spin barrier is
// deadlock-free, and every SM carries identical work so barrier skew ~ 0).
// Phase A: per-roi IoU max/argmax over K gt boxes (lean division-free loop),
//          focal weights (original order), fg bitmask.
// Barrier: per-batch software barrier over the 19 blocks sharing b.
// Phase B: warp-local scan of the batch's 260 mask words -> dest index;
//          scatter rois/labels/targets with coords still live in registers.
// ---------------------------------------------------------------------------
__global__ __launch_bounds__(TT, 2)
void k_fused(const float* __restrict__ rois,
             const float* __restrict__ gt,
             float* __restrict__ out) {
    const int b = blockIdx.y;
    const int t = threadIdx.x;
    const int m = blockIdx.x * TT + t;
    const bool valid = (m < Mm);
    const int mm = valid ? m : (Mm - 1);

    __shared__ float4 sc[Kk];                    // gx1, gy1, gx2+1 (-1e30 if zero-area), gy2+1
    __shared__ __align__(16) float ssar[Kk];     // gt area (reference expression)
    __shared__ float slab[Kk];                   // gt label

    const float* gtb = gt + (size_t)b * Kk * 5;
    if (t < Kk) {
        float x1 = gtb[t * 5 + 0], y1 = gtb[t * 5 + 1];
        float x2 = gtb[t * 5 + 2], y2 = gtb[t * 5 + 3];
        float w = x2 - x1 + 1.0f, h = y2 - y1 + 1.0f;
        bool zf = (w == 1.0f) && (h == 1.0f);
        sc[t] = make_float4(x1, y1, zf ? -1e30f : (x2 + 1.0f), y2 + 1.0f);
        ssar[t] = w * h;
        slab[t] = gtb[t * 5 + 4];
    }
    __syncthreads();

    float x1, y1, x2, y2;
    if (mm < Nn) { const float* p = rois + ((size_t)b * Nn + mm) * 5;
                   x1 = p[1]; y1 = p[2]; x2 = p[3]; y2 = p[4]; }
    else         { const float* p = gtb + (size_t)(mm - Nn) * 5;
                   x1 = p[0]; y1 = p[1]; x2 = p[2]; y2 = p[3]; }
    const float aw = x2 - x1 + 1.0f;
    const float ah = y2 - y1 + 1.0f;
    const float aA = aw * ah;
    const float X2p = x2 + 1.0f, Y2p = y2 + 1.0f;

    float bI = 0.0f, bS = 1.0f;
    int arg = 0;

    #pragma unroll 2
    for (int kk = 0; kk < Kk; kk += 4) {
        const float4 sa4 = *(const float4*)&ssar[kk];
        const float sas[4] = {sa4.x, sa4.y, sa4.z, sa4.w};
        #pragma unroll
        for (int j = 0; j < 4; ++j) {
            const int k = kk + j;
            const float4 c = sc[k];
            float iw = fmaxf(fminf(X2p, c.z) - fmaxf(x1, c.x), 0.0f);
            float ih = fminf(Y2p, c.w) - fmaxf(y1, c.y);   // unclamped: ih<0 -> in_<=0 never wins
            float in_ = iw * ih;
            float S = aA + sas[j];
            bool p = in_ * bS > bI * S;
            bI = p ? in_ : bI;
            bS = p ? S : bS;
            arg = p ? k : arg;
        }
    }

    float mo; int a; bool fg;
    if ((aw == 1.0f) && (ah == 1.0f)) {        // zero-area roi (absent in data)
        mo = -1.0f; fg = false; a = 0;
    } else if (m >= Nn) {                      // appended gt: self-IoU == 1 exactly
        mo = 1.0f; fg = true; a = m - Nn;
    } else {
        mo = bI / (bS - bI);                   // one exact div, reference expression
        fg = (mo >= 0.5f);
        a = arg;
    }
    fg = fg && valid;
    const unsigned bal = __ballot_sync(0xffffffffu, fg);
    if (valid) {
        const int idx = b * Mm + m;
        const float om = 1.0f - mo;
        const float w = fg ? om * om : 0.0f;
        const float ow = (w > 0.0f) ? 1.0f : 0.0f;
        ((float4*)(out + OFF_IW))[idx] = make_float4(w, w, w, w);
        ((float4*)(out + OFF_OW))[idx] = make_float4(ow, ow, ow, ow);
        if ((t & 31) == 0) g_mask[b * Ww + (m >> 5)] = bal;   // words 0..259 each written once
    }

    // ---- per-batch barrier (monotone tickets) ----
    __syncthreads();                     // all warps of this block wrote their mask word
    if (t == 0) {
        __threadfence();                 // publish mask words
        const int ticket = atomicAdd(&g_cnt[b], 1);
        const int target = (ticket / GX + 1) * GX;
        while (atomicAdd(&g_cnt[b], 0) < target) __nanosleep(64);
        __threadfence();                 // acquire other blocks' mask words
    }
    __syncthreads();

    if (!valid) return;

    // ---- warp-local prefix over the batch's mask words (no smem, no syncs) ----
    const int word = m >> 5;             // warp-uniform (TT multiple of 32)
    const int lane = t & 31;
    int tot = 0, pre = 0;
    unsigned myw = 0;
    #pragma unroll 4
    for (int w = lane; w < Ww; w += 32) {  // coalesced, L2-hot (16KB table)
        const unsigned mk = g_mask[b * Ww + w];
        const int c = __popc(mk);
        tot += c;
        if (w < word) pre += c;
        if (w == word) myw = mk;
    }
    #pragma unroll
    for (int o = 16; o > 0; o >>= 1) {
        tot += __shfl_xor_sync(0xffffffffu, tot, o);
        pre += __shfl_xor_sync(0xffffffffu, pre, o);
    }
    myw = __shfl_sync(0xffffffffu, myw, word & 31);
    pre += __popc(myw & ((1u << lane) - 1u));       // fg before m within word
    const int d = fg ? pre : tot + (m - pre);

    // ---- scatter with live registers ----
    float* rb = out + OFF_ROIS + ((size_t)b * Mm + d) * 5;
    rb[0] = (float)b; rb[1] = x1; rb[2] = y1; rb[3] = x2; rb[4] = y2;

    float lab = 0.0f;
    float t0 = 0.0f, t1 = 0.0f, t2 = 0.0f, t3 = 0.0f;
    if (fg) {
        const float4 c = sc[a];                    // assigned gt, smem-resident
        lab = slab[a];                             // labels in {1..3}
        float ew = x2 - x1 + 1.0f, eh = y2 - y1 + 1.0f;
        float ecx = x1 + 0.5f * ew, ecy = y1 + 0.5f * eh;
        float gw = c.z - c.x, gh = c.w - c.y;      // (x2+1)-x1: <=1 ulp vs reference
        float gcx = c.x + 0.5f * gw, gcy = c.y + 0.5f * gh;
        t0 = ((gcx - ecx) / ew) / 0.1f;
        t1 = ((gcy - ecy) / eh) / 0.1f;
        t2 = logf(gw / ew) / 0.2f;
        t3 = logf(gh / eh) / 0.2f;
    }
    out[OFF_LAB + (size_t)b * Mm + d] = lab;
    ((float4*)(out + OFF_TGT))[(size_t)b * Mm + d] = make_float4(t0, t1, t2, t3);
}

extern "C" void kernel_launch(void* const* d_in, const int* in_sizes, int n_in,
                              void* d_out, int out_size) {
    const float* rois = (const float*)d_in[0];   // (B, N, 5)
    const float* gt   = (const float*)d_in[1];   // (B, K, 5)
    float* out = (float*)d_out;

    dim3 grid(GX, Bb);                           // 19 x 16 = 304 blocks = 2/SM exactly
    k_fused<<<grid, TT>>>(rois, gt, out);
}